// round 14
// baseline (speedup 1.0000x reference)
#include <cuda_runtime.h>
#include <math_constants.h>

// Problem constants
#define VOCAB   1024
#define EMBED   64
#define NTOK    65536           // 64 * 32 * 32
#define CHUNK   128             // codes per smem tile
#define ZQ_ELEMS 4194304        // 64*64*32*32
#define IDX_OFF  ZQ_ELEMS       // indices start
#define SCAL_OFF (ZQ_ELEMS + NTOK)

// Device-global scratch (allocation-free rule)
__device__ float  g_se[VOCAB];
__device__ int    g_counts[VOCAB];
__device__ double g_loss;

// ---------------------------------------------------------------------------
// Kernel 1: per-code squared norms, zero accumulators. Deterministic per call.
// ---------------------------------------------------------------------------
__global__ void vq_init(const float* __restrict__ emb) {
    int v = blockIdx.x * blockDim.x + threadIdx.x;
    if (v < VOCAB) {
        const float* e = emb + (size_t)v * EMBED;
        float s = 0.0f;
        #pragma unroll
        for (int i = 0; i < EMBED; i++)
            s = __fadd_rn(s, __fmul_rn(e[i], e[i]));   // mul-then-add, no FMA fuse
        g_se[v] = s;
        g_counts[v] = 0;
    }
    if (v == 0) g_loss = 0.0;
}

// ---------------------------------------------------------------------------
// Kernel 2: fused distances + argmin + gather + z_q_st + loss + histogram.
// One token per thread; z row held in 64 registers; codes streamed through
// smem in 128-code chunks (broadcast LDS, conflict-free).
// ---------------------------------------------------------------------------
__global__ __launch_bounds__(256, 2)
void vq_main(const float* __restrict__ ze,
             const float* __restrict__ emb,
             float* __restrict__ out) {
    __shared__ float  sh_e[CHUNK * EMBED];   // 32 KB
    __shared__ float  sh_se[CHUNK];
    __shared__ int    sh_hist[VOCAB];        // 4 KB
    __shared__ double sh_red[256];           // 2 KB

    const int t = threadIdx.x;
    for (int i = t; i < VOCAB; i += 256) sh_hist[i] = 0;

    const int blk = blockIdx.x;             // 256 blocks
    const int b   = blk >> 2;               // batch
    const int hw  = ((blk & 3) << 8) | t;   // h*32+w, consecutive per thread
    const float* zp = ze + (size_t)b * 65536 + hw;

    // Load token row (coalesced: adjacent threads -> adjacent addresses)
    float z[EMBED];
    #pragma unroll
    for (int i = 0; i < EMBED; i++) z[i] = zp[(size_t)i * 1024];

    // ||z||^2 with explicit rounding (matches sum(z*z): mul then add)
    float sz = 0.0f;
    #pragma unroll
    for (int i = 0; i < EMBED; i++)
        sz = __fadd_rn(sz, __fmul_rn(z[i], z[i]));

    float best = CUDART_INF_F;
    int   bi   = 0;

    for (int c0 = 0; c0 < VOCAB; c0 += CHUNK) {
        __syncthreads();   // protect previous chunk
        {   // cooperative chunk load (embedding is L2-resident: 256 KB)
            const float4* src = (const float4*)(emb + (size_t)c0 * EMBED);
            float4* dst = (float4*)sh_e;
            for (int i = t; i < CHUNK * EMBED / 4; i += 256) dst[i] = src[i];
            if (t < CHUNK) sh_se[t] = g_se[c0 + t];
        }
        __syncthreads();

        for (int c = 0; c < CHUNK; c += 4) {
            const float* e0 = sh_e + c * EMBED;
            const float* e1 = e0 + EMBED;
            const float* e2 = e1 + EMBED;
            const float* e3 = e2 + EMBED;
            float a0 = 0.f, a1 = 0.f, a2 = 0.f, a3 = 0.f;
            #pragma unroll
            for (int i = 0; i < EMBED; i++) {
                const float zi = z[i];
                a0 = __fmaf_rn(zi, e0[i], a0);
                a1 = __fmaf_rn(zi, e1[i], a1);
                a2 = __fmaf_rn(zi, e2[i], a2);
                a3 = __fmaf_rn(zi, e3[i], a3);
            }
            // d = (sz + se) - 2*dot, each op individually rounded (matches XLA)
            const float d0 = __fsub_rn(__fadd_rn(sz, sh_se[c + 0]), __fmul_rn(2.0f, a0));
            const float d1 = __fsub_rn(__fadd_rn(sz, sh_se[c + 1]), __fmul_rn(2.0f, a1));
            const float d2 = __fsub_rn(__fadd_rn(sz, sh_se[c + 2]), __fmul_rn(2.0f, a2));
            const float d3 = __fsub_rn(__fadd_rn(sz, sh_se[c + 3]), __fmul_rn(2.0f, a3));
            // strict < : argmin keeps FIRST (lowest) index on ties, like jnp.argmin
            if (d0 < best) { best = d0; bi = c0 + c + 0; }
            if (d1 < best) { best = d1; bi = c0 + c + 1; }
            if (d2 < best) { best = d2; bi = c0 + c + 2; }
            if (d3 < best) { best = d3; bi = c0 + c + 3; }
        }
    }

    // histogram (block-local then merged)
    atomicAdd(&sh_hist[bi], 1);

    // z_q gather, z_q_st = z_e + (z_q - z_e) with fp32 rounding, loss terms
    const float* er = emb + (size_t)bi * EMBED;
    float* op = out + (size_t)b * 65536 + hw;
    double ls = 0.0;
    #pragma unroll
    for (int i = 0; i < EMBED; i++) {
        const float zq = er[i];
        const float df = __fsub_rn(zq, z[i]);          // (z_q - z_e)
        op[(size_t)i * 1024] = __fadd_rn(z[i], df);    // z_q_st
        const float sq = __fmul_rn(df, df);            // squared in fp32 like ref
        ls += (double)sq;                              // exact-ish accumulation
    }

    // indices output (cast to float per output-buffer dtype)
    out[IDX_OFF + (size_t)b * 1024 + hw] = (float)bi;

    // block reduce loss sum -> global double atomic
    sh_red[t] = ls;
    __syncthreads();
    for (int s = 128; s > 0; s >>= 1) {
        if (t < s) sh_red[t] += sh_red[t + s];
        __syncthreads();
    }
    if (t == 0) atomicAdd(&g_loss, sh_red[0]);

    // merge histogram
    for (int i = t; i < VOCAB; i += 256) {
        const int c = sh_hist[i];
        if (c) atomicAdd(&g_counts[i], c);
    }
}

// ---------------------------------------------------------------------------
// Kernel 3: scalars (quant loss, commit loss, perplexity)
// ---------------------------------------------------------------------------
__global__ void vq_final(float* __restrict__ out) {
    __shared__ double sh[256];
    const int t = threadIdx.x;
    double s = 0.0;
    for (int v = t; v < VOCAB; v += 256) {
        // counts/65536: exact power-of-two scale
        const float p = __fmul_rn((float)g_counts[v], (1.0f / 65536.0f));
        const float term = __fmul_rn(p, logf(__fadd_rn(p, 1e-10f)));
        s += (double)term;
    }
    sh[t] = s;
    __syncthreads();
    for (int k = 128; k > 0; k >>= 1) {
        if (t < k) sh[t] += sh[t + k];
        __syncthreads();
    }
    if (t == 0) {
        const float q = (float)(g_loss / (double)ZQ_ELEMS);
        out[SCAL_OFF + 0] = q;                       // quantization_loss
        out[SCAL_OFF + 1] = __fmul_rn(q, 0.25f);     // commitment_loss
        out[SCAL_OFF + 2] = expf(-(float)sh[0]);     // perplexity
    }
}

// ---------------------------------------------------------------------------
extern "C" void kernel_launch(void* const* d_in, const int* in_sizes, int n_in,
                              void* d_out, int out_size) {
    const float* z_e = (const float*)d_in[0];   // [64,64,32,32] float32
    const float* emb = (const float*)d_in[1];   // [1024,64]     float32
    float* out = (float*)d_out;

    vq_init<<<4, 256>>>(emb);
    vq_main<<<256, 256>>>(z_e, emb, out);
    vq_final<<<1, 256>>>(out);
}

// round 15
// speedup vs baseline: 1.0034x; 1.0034x over previous
#include <cuda_runtime.h>
#include <math_constants.h>

// Problem constants
#define VOCAB   1024
#define EMBED   64
#define NTOK    65536           // 64 * 32 * 32
#define CHUNK   128             // codes per smem tile
#define ZQ_ELEMS 4194304        // 64*64*32*32
#define IDX_OFF  ZQ_ELEMS       // indices start
#define SCAL_OFF (ZQ_ELEMS + NTOK)

// Device-global scratch (allocation-free rule)
__device__ float  g_se[VOCAB];
__device__ int    g_counts[VOCAB];
__device__ double g_loss;

// ---------------------------------------------------------------------------
// Kernel 1: per-code squared norms, zero accumulators. Deterministic per call.
// ---------------------------------------------------------------------------
__global__ void vq_init(const float* __restrict__ emb) {
    int v = blockIdx.x * blockDim.x + threadIdx.x;
    if (v < VOCAB) {
        const float* e = emb + (size_t)v * EMBED;
        float s = 0.0f;
        #pragma unroll
        for (int i = 0; i < EMBED; i++)
            s = __fadd_rn(s, __fmul_rn(e[i], e[i]));   // mul-then-add, no FMA fuse
        g_se[v] = s;
        g_counts[v] = 0;
    }
    if (v == 0) g_loss = 0.0;
}

// ---------------------------------------------------------------------------
// Kernel 2: fused distances + argmin + gather + z_q_st + loss + histogram.
// One token per thread; z row held in 64 registers; codes streamed through
// smem in 128-code chunks (broadcast LDS, conflict-free).
// ---------------------------------------------------------------------------
__global__ __launch_bounds__(256, 2)
void vq_main(const float* __restrict__ ze,
             const float* __restrict__ emb,
             float* __restrict__ out) {
    __shared__ float  sh_e[CHUNK * EMBED];   // 32 KB
    __shared__ float  sh_se[CHUNK];
    __shared__ int    sh_hist[VOCAB];        // 4 KB
    __shared__ double sh_red[256];           // 2 KB

    const int t = threadIdx.x;
    for (int i = t; i < VOCAB; i += 256) sh_hist[i] = 0;

    const int blk = blockIdx.x;             // 256 blocks
    const int b   = blk >> 2;               // batch
    const int hw  = ((blk & 3) << 8) | t;   // h*32+w, consecutive per thread
    const float* zp = ze + (size_t)b * 65536 + hw;

    // Load token row (coalesced: adjacent threads -> adjacent addresses)
    float z[EMBED];
    #pragma unroll
    for (int i = 0; i < EMBED; i++) z[i] = zp[(size_t)i * 1024];

    // ||z||^2 with explicit rounding (matches sum(z*z): mul then add)
    float sz = 0.0f;
    #pragma unroll
    for (int i = 0; i < EMBED; i++)
        sz = __fadd_rn(sz, __fmul_rn(z[i], z[i]));

    float best = CUDART_INF_F;
    int   bi   = 0;

    for (int c0 = 0; c0 < VOCAB; c0 += CHUNK) {
        __syncthreads();   // protect previous chunk
        {   // cooperative chunk load (embedding is L2-resident: 256 KB)
            const float4* src = (const float4*)(emb + (size_t)c0 * EMBED);
            float4* dst = (float4*)sh_e;
            for (int i = t; i < CHUNK * EMBED / 4; i += 256) dst[i] = src[i];
            if (t < CHUNK) sh_se[t] = g_se[c0 + t];
        }
        __syncthreads();

        for (int c = 0; c < CHUNK; c += 4) {
            const float* e0 = sh_e + c * EMBED;
            const float* e1 = e0 + EMBED;
            const float* e2 = e1 + EMBED;
            const float* e3 = e2 + EMBED;
            float a0 = 0.f, a1 = 0.f, a2 = 0.f, a3 = 0.f;
            #pragma unroll
            for (int i = 0; i < EMBED; i++) {
                const float zi = z[i];
                a0 = __fmaf_rn(zi, e0[i], a0);
                a1 = __fmaf_rn(zi, e1[i], a1);
                a2 = __fmaf_rn(zi, e2[i], a2);
                a3 = __fmaf_rn(zi, e3[i], a3);
            }
            // d = (sz + se) - 2*dot, each op individually rounded (matches XLA)
            const float d0 = __fsub_rn(__fadd_rn(sz, sh_se[c + 0]), __fmul_rn(2.0f, a0));
            const float d1 = __fsub_rn(__fadd_rn(sz, sh_se[c + 1]), __fmul_rn(2.0f, a1));
            const float d2 = __fsub_rn(__fadd_rn(sz, sh_se[c + 2]), __fmul_rn(2.0f, a2));
            const float d3 = __fsub_rn(__fadd_rn(sz, sh_se[c + 3]), __fmul_rn(2.0f, a3));
            // strict < : argmin keeps FIRST (lowest) index on ties, like jnp.argmin
            if (d0 < best) { best = d0; bi = c0 + c + 0; }
            if (d1 < best) { best = d1; bi = c0 + c + 1; }
            if (d2 < best) { best = d2; bi = c0 + c + 2; }
            if (d3 < best) { best = d3; bi = c0 + c + 3; }
        }
    }

    // histogram (block-local then merged)
    atomicAdd(&sh_hist[bi], 1);

    // z_q gather, z_q_st = z_e + (z_q - z_e) with fp32 rounding, loss terms
    const float* er = emb + (size_t)bi * EMBED;
    float* op = out + (size_t)b * 65536 + hw;
    double ls = 0.0;
    #pragma unroll
    for (int i = 0; i < EMBED; i++) {
        const float zq = er[i];
        const float df = __fsub_rn(zq, z[i]);          // (z_q - z_e)
        op[(size_t)i * 1024] = __fadd_rn(z[i], df);    // z_q_st
        const float sq = __fmul_rn(df, df);            // squared in fp32 like ref
        ls += (double)sq;                              // exact-ish accumulation
    }

    // indices output (cast to float per output-buffer dtype)
    out[IDX_OFF + (size_t)b * 1024 + hw] = (float)bi;

    // block reduce loss sum -> global double atomic
    sh_red[t] = ls;
    __syncthreads();
    for (int s = 128; s > 0; s >>= 1) {
        if (t < s) sh_red[t] += sh_red[t + s];
        __syncthreads();
    }
    if (t == 0) atomicAdd(&g_loss, sh_red[0]);

    // merge histogram
    for (int i = t; i < VOCAB; i += 256) {
        const int c = sh_hist[i];
        if (c) atomicAdd(&g_counts[i], c);
    }
}

// ---------------------------------------------------------------------------
// Kernel 3: scalars (quant loss, commit loss, perplexity)
// ---------------------------------------------------------------------------
__global__ void vq_final(float* __restrict__ out) {
    __shared__ double sh[256];
    const int t = threadIdx.x;
    double s = 0.0;
    for (int v = t; v < VOCAB; v += 256) {
        // counts/65536: exact power-of-two scale
        const float p = __fmul_rn((float)g_counts[v], (1.0f / 65536.0f));
        const float term = __fmul_rn(p, logf(__fadd_rn(p, 1e-10f)));
        s += (double)term;
    }
    sh[t] = s;
    __syncthreads();
    for (int k = 128; k > 0; k >>= 1) {
        if (t < k) sh[t] += sh[t + k];
        __syncthreads();
    }
    if (t == 0) {
        const float q = (float)(g_loss / (double)ZQ_ELEMS);
        out[SCAL_OFF + 0] = q;                       // quantization_loss
        out[SCAL_OFF + 1] = __fmul_rn(q, 0.25f);     // commitment_loss
        out[SCAL_OFF + 2] = expf(-(float)sh[0]);     // perplexity
    }
}

// ---------------------------------------------------------------------------
extern "C" void kernel_launch(void* const* d_in, const int* in_sizes, int n_in,
                              void* d_out, int out_size) {
    const float* z_e = (const float*)d_in[0];   // [64,64,32,32] float32
    const float* emb = (const float*)d_in[1];   // [1024,64]     float32
    float* out = (float*)d_out;

    vq_init<<<4, 256>>>(emb);
    vq_main<<<256, 256>>>(z_e, emb, out);
    vq_final<<<1, 256>>>(out);
}

// round 16
// speedup vs baseline: 1.0044x; 1.0010x over previous
#include <cuda_runtime.h>
#include <math_constants.h>

// Problem constants
#define VOCAB   1024
#define EMBED   64
#define NTOK    65536           // 64 * 32 * 32
#define CHUNK   128             // codes per smem tile
#define ZQ_ELEMS 4194304        // 64*64*32*32
#define IDX_OFF  ZQ_ELEMS       // indices start
#define SCAL_OFF (ZQ_ELEMS + NTOK)

// Device-global scratch (allocation-free rule)
__device__ float  g_se[VOCAB];
__device__ int    g_counts[VOCAB];
__device__ double g_loss;

// ---------------------------------------------------------------------------
// Kernel 1: per-code squared norms, zero accumulators. Deterministic per call.
// ---------------------------------------------------------------------------
__global__ void vq_init(const float* __restrict__ emb) {
    int v = blockIdx.x * blockDim.x + threadIdx.x;
    if (v < VOCAB) {
        const float* e = emb + (size_t)v * EMBED;
        float s = 0.0f;
        #pragma unroll
        for (int i = 0; i < EMBED; i++)
            s = __fadd_rn(s, __fmul_rn(e[i], e[i]));   // mul-then-add, no FMA fuse
        g_se[v] = s;
        g_counts[v] = 0;
    }
    if (v == 0) g_loss = 0.0;
}

// ---------------------------------------------------------------------------
// Kernel 2: fused distances + argmin + gather + z_q_st + loss + histogram.
// One token per thread; z row held in 64 registers; codes streamed through
// smem in 128-code chunks (broadcast LDS, conflict-free).
// ---------------------------------------------------------------------------
__global__ __launch_bounds__(256, 2)
void vq_main(const float* __restrict__ ze,
             const float* __restrict__ emb,
             float* __restrict__ out) {
    __shared__ float  sh_e[CHUNK * EMBED];   // 32 KB
    __shared__ float  sh_se[CHUNK];
    __shared__ int    sh_hist[VOCAB];        // 4 KB
    __shared__ double sh_red[256];           // 2 KB

    const int t = threadIdx.x;
    for (int i = t; i < VOCAB; i += 256) sh_hist[i] = 0;

    const int blk = blockIdx.x;             // 256 blocks
    const int b   = blk >> 2;               // batch
    const int hw  = ((blk & 3) << 8) | t;   // h*32+w, consecutive per thread
    const float* zp = ze + (size_t)b * 65536 + hw;

    // Load token row (coalesced: adjacent threads -> adjacent addresses)
    float z[EMBED];
    #pragma unroll
    for (int i = 0; i < EMBED; i++) z[i] = zp[(size_t)i * 1024];

    // ||z||^2 with explicit rounding (matches sum(z*z): mul then add)
    float sz = 0.0f;
    #pragma unroll
    for (int i = 0; i < EMBED; i++)
        sz = __fadd_rn(sz, __fmul_rn(z[i], z[i]));

    float best = CUDART_INF_F;
    int   bi   = 0;

    for (int c0 = 0; c0 < VOCAB; c0 += CHUNK) {
        __syncthreads();   // protect previous chunk
        {   // cooperative chunk load (embedding is L2-resident: 256 KB)
            const float4* src = (const float4*)(emb + (size_t)c0 * EMBED);
            float4* dst = (float4*)sh_e;
            for (int i = t; i < CHUNK * EMBED / 4; i += 256) dst[i] = src[i];
            if (t < CHUNK) sh_se[t] = g_se[c0 + t];
        }
        __syncthreads();

        for (int c = 0; c < CHUNK; c += 4) {
            const float* e0 = sh_e + c * EMBED;
            const float* e1 = e0 + EMBED;
            const float* e2 = e1 + EMBED;
            const float* e3 = e2 + EMBED;
            float a0 = 0.f, a1 = 0.f, a2 = 0.f, a3 = 0.f;
            #pragma unroll
            for (int i = 0; i < EMBED; i++) {
                const float zi = z[i];
                a0 = __fmaf_rn(zi, e0[i], a0);
                a1 = __fmaf_rn(zi, e1[i], a1);
                a2 = __fmaf_rn(zi, e2[i], a2);
                a3 = __fmaf_rn(zi, e3[i], a3);
            }
            // d = (sz + se) - 2*dot, each op individually rounded (matches XLA)
            const float d0 = __fsub_rn(__fadd_rn(sz, sh_se[c + 0]), __fmul_rn(2.0f, a0));
            const float d1 = __fsub_rn(__fadd_rn(sz, sh_se[c + 1]), __fmul_rn(2.0f, a1));
            const float d2 = __fsub_rn(__fadd_rn(sz, sh_se[c + 2]), __fmul_rn(2.0f, a2));
            const float d3 = __fsub_rn(__fadd_rn(sz, sh_se[c + 3]), __fmul_rn(2.0f, a3));
            // strict < : argmin keeps FIRST (lowest) index on ties, like jnp.argmin
            if (d0 < best) { best = d0; bi = c0 + c + 0; }
            if (d1 < best) { best = d1; bi = c0 + c + 1; }
            if (d2 < best) { best = d2; bi = c0 + c + 2; }
            if (d3 < best) { best = d3; bi = c0 + c + 3; }
        }
    }

    // histogram (block-local then merged)
    atomicAdd(&sh_hist[bi], 1);

    // z_q gather, z_q_st = z_e + (z_q - z_e) with fp32 rounding, loss terms
    const float* er = emb + (size_t)bi * EMBED;
    float* op = out + (size_t)b * 65536 + hw;
    double ls = 0.0;
    #pragma unroll
    for (int i = 0; i < EMBED; i++) {
        const float zq = er[i];
        const float df = __fsub_rn(zq, z[i]);          // (z_q - z_e)
        op[(size_t)i * 1024] = __fadd_rn(z[i], df);    // z_q_st
        const float sq = __fmul_rn(df, df);            // squared in fp32 like ref
        ls += (double)sq;                              // exact-ish accumulation
    }

    // indices output (cast to float per output-buffer dtype)
    out[IDX_OFF + (size_t)b * 1024 + hw] = (float)bi;

    // block reduce loss sum -> global double atomic
    sh_red[t] = ls;
    __syncthreads();
    for (int s = 128; s > 0; s >>= 1) {
        if (t < s) sh_red[t] += sh_red[t + s];
        __syncthreads();
    }
    if (t == 0) atomicAdd(&g_loss, sh_red[0]);

    // merge histogram
    for (int i = t; i < VOCAB; i += 256) {
        const int c = sh_hist[i];
        if (c) atomicAdd(&g_counts[i], c);
    }
}

// ---------------------------------------------------------------------------
// Kernel 3: scalars (quant loss, commit loss, perplexity)
// ---------------------------------------------------------------------------
__global__ void vq_final(float* __restrict__ out) {
    __shared__ double sh[256];
    const int t = threadIdx.x;
    double s = 0.0;
    for (int v = t; v < VOCAB; v += 256) {
        // counts/65536: exact power-of-two scale
        const float p = __fmul_rn((float)g_counts[v], (1.0f / 65536.0f));
        const float term = __fmul_rn(p, logf(__fadd_rn(p, 1e-10f)));
        s += (double)term;
    }
    sh[t] = s;
    __syncthreads();
    for (int k = 128; k > 0; k >>= 1) {
        if (t < k) sh[t] += sh[t + k];
        __syncthreads();
    }
    if (t == 0) {
        const float q = (float)(g_loss / (double)ZQ_ELEMS);
        out[SCAL_OFF + 0] = q;                       // quantization_loss
        out[SCAL_OFF + 1] = __fmul_rn(q, 0.25f);     // commitment_loss
        out[SCAL_OFF + 2] = expf(-(float)sh[0]);     // perplexity
    }
}

// ---------------------------------------------------------------------------
extern "C" void kernel_launch(void* const* d_in, const int* in_sizes, int n_in,
                              void* d_out, int out_size) {
    const float* z_e = (const float*)d_in[0];   // [64,64,32,32] float32
    const float* emb = (const float*)d_in[1];   // [1024,64]     float32
    float* out = (float*)d_out;

    vq_init<<<4, 256>>>(emb);
    vq_main<<<256, 256>>>(z_e, emb, out);
    vq_final<<<1, 256>>>(out);
}